// round 9
// baseline (speedup 1.0000x reference)
#include <cuda_runtime.h>

// Fused depthwise conv: y = gauss_valid(fd_valid(x)) == one 13-tap valid FIR.
// Composed kernel is SYMMETRIC: out[j] = sum_{k<6} w[k]*(x[j+k]+x[j+12-k])
//                                        + w[6]*x[j+6].
//
// x: [8,4,T] f32 -> 32 rows, T = 1048576. out rows: Tout = T-12.
//
// R6: persistent + 2-deep software pipeline. While tile t is computed/stored
// from one register buffer, tile t+1's 4 coalesced LDG.128 are in flight
// into the other buffer (manual unroll-by-2, no reg copies). VPT=4 keeps the
// 16B lane stride (4-line wavefronts) that R4 proved essential.

#define BLOCK 256
#define VPT   4
#define TILE  (BLOCK * VPT)   // 1024 outputs per tile

__device__ __forceinline__
void loadTile(const float* __restrict__ x, int t, int tilesPerRow,
              int T, int tid, float r[16])
{
    const int row  = t / tilesPerRow;
    const int tile = t - row * tilesPerRow;
    const long long xb = (long long)row * T;
    const int gb = tile * TILE + tid * VPT;

    if (gb + 16 <= T) {
        #pragma unroll
        for (int v = 0; v < 4; ++v) {
            float4 f = *(const float4*)(x + xb + gb + 4 * v);
            r[4*v+0] = f.x; r[4*v+1] = f.y;
            r[4*v+2] = f.z; r[4*v+3] = f.w;
        }
    } else {
        #pragma unroll
        for (int i = 0; i < 16; ++i) {
            const int gi = gb + i;
            r[i] = (gi < T) ? x[xb + gi] : 0.f;
        }
    }
}

__device__ __forceinline__
void computeStore(float* __restrict__ out, int t, int tilesPerRow,
                  int Tout, int tid, const float w[7], const float r[16])
{
    const int row  = t / tilesPerRow;
    const int tile = t - row * tilesPerRow;
    const long long ob = (long long)row * Tout;
    const int gb = tile * TILE + tid * VPT;

    float a[4];
    #pragma unroll
    for (int j = 0; j < 4; ++j) {
        float acc = w[6] * r[j + 6];
        #pragma unroll
        for (int k = 0; k < 6; ++k)
            acc = fmaf(w[k], r[j + k] + r[j + 12 - k], acc);
        a[j] = acc;
    }

    if (gb + 4 <= Tout) {
        *(float4*)(out + ob + gb) = make_float4(a[0], a[1], a[2], a[3]);
    } else {
        #pragma unroll
        for (int v = 0; v < 4; ++v)
            if (gb + v < Tout) out[ob + gb + v] = a[v];
    }
}

__global__ __launch_bounds__(BLOCK, 5)
void fused_fir13_pipe(const float* __restrict__ x,
                      const float* __restrict__ fd,   // 5 taps
                      const float* __restrict__ gk,   // 9 taps
                      float* __restrict__ out,
                      int T, int Tout, int tilesPerRow, int tilesTotal)
{
    __shared__ float wsh[7];
    const int tid = threadIdx.x;

    // Compose symmetric half-kernel once per CTA.
    if (tid < 7) {
        float acc = 0.f;
        const int hi = tid < 4 ? tid : 4;
        for (int i = 0; i <= hi; ++i) acc += fd[i] * gk[tid - i];
        wsh[tid] = acc;
    }
    __syncthreads();

    float w[7];
    #pragma unroll
    for (int k = 0; k < 7; ++k) w[k] = wsh[k];

    int t = blockIdx.x;
    if (t >= tilesTotal) return;

    float rA[16], rB[16];
    loadTile(x, t, tilesPerRow, T, tid, rA);

    const int step = gridDim.x;
    for (;;) {
        // Phase A: prefetch t+step into rB, compute t from rA.
        const int t2 = t + step;
        const bool has2 = (t2 < tilesTotal);
        if (has2) loadTile(x, t2, tilesPerRow, T, tid, rB);
        computeStore(out, t, tilesPerRow, Tout, tid, w, rA);
        if (!has2) break;

        // Phase B: prefetch t+2*step into rA, compute t2 from rB.
        const int t3 = t2 + step;
        const bool has3 = (t3 < tilesTotal);
        if (has3) loadTile(x, t3, tilesPerRow, T, tid, rA);
        computeStore(out, t2, tilesPerRow, Tout, tid, w, rB);
        if (!has3) break;

        t = t3;
    }
}

extern "C" void kernel_launch(void* const* d_in, const int* in_sizes, int n_in,
                              void* d_out, int out_size)
{
    const float* x  = (const float*)d_in[0];
    const float* fd = (const float*)d_in[1];   // 5 elements
    const float* gk = (const float*)d_in[2];   // 9 elements
    float* out = (float*)d_out;

    const int ROWS = 32;                       // 8 * 4
    const int T    = in_sizes[0] / ROWS;       // 1048576
    const int Tout = T - 12;                   // 1048564

    const int tilesPerRow = (Tout + TILE - 1) / TILE;   // 1024
    const int tilesTotal  = ROWS * tilesPerRow;         // 32768

    const int SMS = 148, CTAS_PER_SM = 5;
    int blocks = SMS * CTAS_PER_SM;                     // 740 persistent CTAs
    if (blocks > tilesTotal) blocks = tilesTotal;

    fused_fir13_pipe<<<blocks, BLOCK>>>(x, fd, gk, out,
                                        T, Tout, tilesPerRow, tilesTotal);
}

// round 10
// speedup vs baseline: 1.1184x; 1.1184x over previous
#include <cuda_runtime.h>

// Fused depthwise conv: y = gauss_valid(fd_valid(x)) == one 13-tap valid FIR.
// Composed kernel is SYMMETRIC: out[j] = sum_{k<6} w[k]*(x[j+k]+x[j+12-k])
//                                        + w[6]*x[j+6].
//
// x: [8,4,T] f32 -> 32 rows, T = 1048576. out rows: Tout = T-12.
//
// R8: R5 structure (proven best: persistent grid, GROUPS=2 front-batched
// coalesced LDG.128, VPT=4 / 16B lane stride) with slimmed addressing:
//   - all-int32 offsets (whole tensor < 2^27 elements)
//   - tilesPerRow is a power of two -> shift/mask instead of div/mod
//   - launch_bounds(256,6): 42-reg budget -> 48 warps/SM (75% theoretical)

#define BLOCK  256
#define GROUPS 2
#define GTILE  (BLOCK * 4)        // 1024 outputs per group
#define TILE   (GTILE * GROUPS)   // 2048 outputs per tile
#define TPR_LOG2 9                // tilesPerRow = 512 (for T=2^20)

__global__ __launch_bounds__(BLOCK, 6)
void fused_fir13_p6(const float* __restrict__ x,
                    const float* __restrict__ fd,   // 5 taps
                    const float* __restrict__ gk,   // 9 taps
                    float* __restrict__ out,
                    int T, int Tout, int tilesTotal)
{
    __shared__ float wsh[7];
    const int tid = threadIdx.x;

    // Compose symmetric half-kernel once per CTA.
    if (tid < 7) {
        float acc = 0.f;
        const int hi = tid < 4 ? tid : 4;
        for (int i = 0; i <= hi; ++i) acc += fd[i] * gk[tid - i];
        wsh[tid] = acc;
    }
    __syncthreads();

    float w[7];
    #pragma unroll
    for (int k = 0; k < 7; ++k) w[k] = wsh[k];

    for (int t = blockIdx.x; t < tilesTotal; t += gridDim.x) {
        const int row  = t >> TPR_LOG2;                 // uniform
        const int tile = t & ((1 << TPR_LOG2) - 1);     // uniform
        const int xb   = row * T;                       // int32: max ~33.5M
        const int ob   = row * Tout;
        const int start = tile * TILE;

        // ---- Front-batch all loads: 8 coalesced LDG.128 in flight ----
        float r[GROUPS][16];
        #pragma unroll
        for (int q = 0; q < GROUPS; ++q) {
            const int gb = start + q * GTILE + tid * 4;
            if (gb + 16 <= T) {
                #pragma unroll
                for (int v = 0; v < 4; ++v) {
                    float4 f = *(const float4*)(x + xb + gb + 4 * v);
                    r[q][4*v+0] = f.x; r[q][4*v+1] = f.y;
                    r[q][4*v+2] = f.z; r[q][4*v+3] = f.w;
                }
            } else {
                #pragma unroll
                for (int i = 0; i < 16; ++i) {
                    const int gi = gb + i;
                    r[q][i] = (gi < T) ? x[xb + gi] : 0.f;
                }
            }
        }

        // ---- Compute + store per group ----
        #pragma unroll
        for (int q = 0; q < GROUPS; ++q) {
            const int gb = start + q * GTILE + tid * 4;
            float a[4];
            #pragma unroll
            for (int j = 0; j < 4; ++j) {
                float acc = w[6] * r[q][j + 6];
                #pragma unroll
                for (int k = 0; k < 6; ++k)
                    acc = fmaf(w[k], r[q][j + k] + r[q][j + 12 - k], acc);
                a[j] = acc;
            }
            if (gb + 4 <= Tout) {
                *(float4*)(out + ob + gb) = make_float4(a[0], a[1], a[2], a[3]);
            } else {
                #pragma unroll
                for (int v = 0; v < 4; ++v)
                    if (gb + v < Tout) out[ob + gb + v] = a[v];
            }
        }
    }
}

extern "C" void kernel_launch(void* const* d_in, const int* in_sizes, int n_in,
                              void* d_out, int out_size)
{
    const float* x  = (const float*)d_in[0];
    const float* fd = (const float*)d_in[1];   // 5 elements
    const float* gk = (const float*)d_in[2];   // 9 elements
    float* out = (float*)d_out;

    const int ROWS = 32;                       // 8 * 4
    const int T    = in_sizes[0] / ROWS;       // 1048576
    const int Tout = T - 12;                   // 1048564

    const int tilesPerRow = 1 << TPR_LOG2;              // 512 (= ceil(Tout/TILE))
    const int tilesTotal  = ROWS * tilesPerRow;         // 16384

    const int SMS = 148, CTAS_PER_SM = 6;
    int blocks = SMS * CTAS_PER_SM;                     // 888 persistent CTAs
    if (blocks > tilesTotal) blocks = tilesTotal;

    fused_fir13_p6<<<blocks, BLOCK>>>(x, fd, gk, out, T, Tout, tilesTotal);
}